// round 3
// baseline (speedup 1.0000x reference)
#include <cuda_runtime.h>
#include <cuda_bf16.h>
#include <cstdint>

// B=16, T=4096 -> N=65536 tokens, D=64, K=1024
#define D 64
#define K 1024
#define BM 256          // tokens per CTA
#define BK 64           // codes staged per chunk
#define NC (K / BK)     // 16 chunks
#define THREADS 128     // tx=8 (codes), ty=16 (token groups)

__device__ float g_embedT[K * D];  // [k][d]
__device__ float g_h[K];           // 0.5 * ||e_k||^2

typedef unsigned long long ull;

__device__ __forceinline__ ull ffma2(ull a, ull b, ull c) {
    ull d_;
    asm("fma.rn.f32x2 %0, %1, %2, %3;" : "=l"(d_) : "l"(a), "l"(b), "l"(c));
    return d_;
}
__device__ __forceinline__ ull dup_f32(float x) {
    ull r;
    asm("mov.b64 %0, {%1, %1};" : "=l"(r) : "f"(x));
    return r;
}
__device__ __forceinline__ float2 unpack2(ull a) {
    float2 u;
    asm("mov.b64 {%0, %1}, %2;" : "=f"(u.x), "=f"(u.y) : "l"(a));
    return u;
}
__device__ __forceinline__ void cp16(uint32_t s, const void* g) {
    asm volatile("cp.async.cg.shared.global [%0], [%1], 16;" :: "r"(s), "l"(g));
}

// ---------------- prep: transpose codebook + half code norms ----------------
__global__ void vq_prep(const float* __restrict__ embed) {
    int i = blockIdx.x * blockDim.x + threadIdx.x;
    if (i < K * D) {
        int k = i >> 6;
        int d = i & 63;
        g_embedT[i] = embed[d * K + k];
    }
    if (i < K) {
        float s = 0.f;
        #pragma unroll
        for (int d = 0; d < D; d++) {
            float v = embed[d * K + i];
            s = fmaf(v, v, s);
        }
        g_h[i] = 0.5f * s;
    }
}

// ---------------- main: fused distance GEMM + argmin + gather ----------------
__global__ __launch_bounds__(THREADS, 1)
void vq_main(const float* __restrict__ input,
             const float* __restrict__ embed,
             float* __restrict__ q_out,
             float* __restrict__ diff_out,
             float* __restrict__ ind_out) {
    extern __shared__ char smem_raw[];
    float* xs = (float*)smem_raw;                  // [D][BM] transposed x (token-major pairs)
    float* es = xs + D * BM;                       // [2][D][BK]
    float* hs = es + 2 * D * BK;                   // [K]
    int*   best_sm = (int*)(hs + K);               // [BM]

    const int tid = threadIdx.x;
    const int tx  = tid & 7;    // 8 thread-cols * TN=8 codes -> BK=64
    const int ty  = tid >> 3;   // 16 thread-rows * TM=16 tokens -> BM=256
    const int n0  = blockIdx.x * BM;

    // ---- prologue: x tile, coalesced read -> transposed shared [d][token] ----
    const float4* in4 = reinterpret_cast<const float4*>(input + (size_t)n0 * D);
    #pragma unroll
    for (int t = tid; t < BM * D / 4; t += THREADS) {
        float4 v = in4[t];
        int row = t >> 4;              // token in tile (0..255)
        int c   = (t & 15) << 2;       // starting d
        xs[(c + 0) * BM + row] = v.x;
        xs[(c + 1) * BM + row] = v.y;
        xs[(c + 2) * BM + row] = v.z;
        xs[(c + 3) * BM + row] = v.w;
    }
    #pragma unroll
    for (int t = tid; t < K; t += THREADS) hs[t] = g_h[t];

    uint32_t es_s = (uint32_t)__cvta_generic_to_shared(es);

    // ---- prefetch chunk 0 (cp.async): D*BK floats = 1024 float4 ----
    #pragma unroll
    for (int i = 0; i < 8; i++) {
        int idx = i * THREADS + tid;
        int d = idx >> 4, c4 = (idx & 15) << 2;
        cp16(es_s + (uint32_t)(d * BK + c4) * 4, embed + (size_t)d * K + c4);
    }
    asm volatile("cp.async.commit_group;");

    // per-thread best over 16 local tokens (pairs 0..7, halves)
    float best_s[16];
    int   best_i[16];
    #pragma unroll
    for (int i = 0; i < 16; i++) { best_s[i] = 3.4e38f; best_i[i] = 0; }

    const ull* xrow = (const ull*)xs + ty * 8;    // 8 token-pairs, stride BM/2=128 ull per d

    for (int ck = 0; ck < NC; ck++) {
        asm volatile("cp.async.wait_group 0;");
        __syncthreads();   // chunk ck visible; all warps done with the other buffer

        if (ck + 1 < NC) {
            int kb2 = (ck + 1) * BK;
            uint32_t dst = es_s + (uint32_t)(((ck + 1) & 1) * D * BK) * 4;
            #pragma unroll
            for (int i = 0; i < 8; i++) {
                int idx = i * THREADS + tid;
                int d = idx >> 4, c4 = (idx & 15) << 2;
                cp16(dst + (uint32_t)(d * BK + c4) * 4,
                     embed + (size_t)d * K + kb2 + c4);
            }
            asm volatile("cp.async.commit_group;");
        }

        const float* ebt = es + (ck & 1) * D * BK + tx * 8;

        ull acc[8][8];   // [code][token-pair]
        #pragma unroll
        for (int c = 0; c < 8; c++)
            #pragma unroll
            for (int p = 0; p < 8; p++) acc[c][p] = 0ULL;

        #pragma unroll 4
        for (int d = 0; d < D; d++) {
            ulonglong2 x01 = *(const ulonglong2*)(xrow + d * (BM / 2) + 0);
            ulonglong2 x23 = *(const ulonglong2*)(xrow + d * (BM / 2) + 2);
            ulonglong2 x45 = *(const ulonglong2*)(xrow + d * (BM / 2) + 4);
            ulonglong2 x67 = *(const ulonglong2*)(xrow + d * (BM / 2) + 6);
            float4 ea = *(const float4*)(ebt + d * BK);
            float4 eb = *(const float4*)(ebt + d * BK + 4);

            ull xv[8] = {x01.x, x01.y, x23.x, x23.y, x45.x, x45.y, x67.x, x67.y};
            ull ev[8];
            ev[0] = dup_f32(ea.x); ev[1] = dup_f32(ea.y);
            ev[2] = dup_f32(ea.z); ev[3] = dup_f32(ea.w);
            ev[4] = dup_f32(eb.x); ev[5] = dup_f32(eb.y);
            ev[6] = dup_f32(eb.z); ev[7] = dup_f32(eb.w);

            #pragma unroll
            for (int c = 0; c < 8; c++) {
                #pragma unroll
                for (int p = 0; p < 8; p++) {
                    acc[c][p] = ffma2(xv[p], ev[c], acc[c][p]);
                }
            }
        }

        // ---- scores + running argmin (ascending k keeps lowest-index tie) ----
        int kb = ck * BK;
        float4 hA = *(const float4*)(hs + kb + tx * 8);
        float4 hB = *(const float4*)(hs + kb + tx * 8 + 4);
        float hv[8] = {hA.x, hA.y, hA.z, hA.w, hB.x, hB.y, hB.z, hB.w};

        #pragma unroll
        for (int c = 0; c < 8; c++) {
            int k0 = kb + tx * 8 + c;
            #pragma unroll
            for (int p = 0; p < 8; p++) {
                float2 pr = unpack2(acc[c][p]);
                float s0 = hv[c] - pr.x;
                float s1 = hv[c] - pr.y;
                if (s0 < best_s[2 * p])     { best_s[2 * p]     = s0; best_i[2 * p]     = k0; }
                if (s1 < best_s[2 * p + 1]) { best_s[2 * p + 1] = s1; best_i[2 * p + 1] = k0; }
            }
        }
    }

    // ---- reduce across the 8 tx lanes (xor 4,2,1 stays inside the 8-group) ----
    #pragma unroll
    for (int j = 0; j < 16; j++) {
        float s = best_s[j];
        int   bi = best_i[j];
        #pragma unroll
        for (int m = 4; m >= 1; m >>= 1) {
            float so = __shfl_xor_sync(0xffffffffu, s, m);
            int   io = __shfl_xor_sync(0xffffffffu, bi, m);
            if (so < s || (so == s && io < bi)) { s = so; bi = io; }
        }
        if (tx == 0) {
            int row = ty * 16 + j;
            best_sm[row] = bi;
            if (ind_out) ind_out[n0 + row] = (float)bi;
        }
    }
    __syncthreads();

    // ---- gather quantize + diff; x re-read from global (coalesced) ----
    #pragma unroll
    for (int t = tid; t < BM * D / 4; t += THREADS) {
        int row = t >> 4;
        int c   = (t & 15) << 2;
        int kq  = best_sm[row];
        float4 q = *(const float4*)(g_embedT + kq * D + c);
        float4 x = in4[t];
        size_t o = (size_t)(n0 + row) * D + c;
        *reinterpret_cast<float4*>(&q_out[o]) = q;
        if (diff_out) {
            float4 df;
            df.x = (q.x - x.x) * (q.x - x.x);
            df.y = (q.y - x.y) * (q.y - x.y);
            df.z = (q.z - x.z) * (q.z - x.z);
            df.w = (q.w - x.w) * (q.w - x.w);
            *reinterpret_cast<float4*>(&diff_out[o]) = df;
        }
    }
}

#define SMEM_BYTES ((size_t)D * BM * 4 + 2 * D * BK * 4 + K * 4 + BM * 4)

extern "C" void kernel_launch(void* const* d_in, const int* in_sizes, int n_in,
                              void* d_out, int out_size) {
    const float* input = (const float*)d_in[0];   // [B,T,D] fp32
    const float* embed = (const float*)d_in[1];   // [D,K]   fp32

    const int N = in_sizes[0] / D;
    const long nd = (long)N * D;

    float* out = (float*)d_out;
    float* q_out    = out;
    float* diff_out = nullptr;
    float* ind_out  = nullptr;
    if ((long)out_size >= 2 * nd + N) { diff_out = out + nd; ind_out = out + 2 * nd; }
    else if ((long)out_size >= 2 * nd) { diff_out = out + nd; }

    cudaFuncSetAttribute(vq_main, cudaFuncAttributeMaxDynamicSharedMemorySize, (int)SMEM_BYTES);

    vq_prep<<<(K * D + 255) / 256, 256>>>(embed);
    vq_main<<<N / BM, THREADS, SMEM_BYTES>>>(input, embed, q_out, diff_out, ind_out);
}